// round 1
// baseline (speedup 1.0000x reference)
#include <cuda_runtime.h>
#include <cstdint>
#include <cmath>

typedef unsigned long long u64;

#define NT 224                  // threads per CTA (7 warps)
#define PM 4560                 // floats per muscle block in smem
#define OFF_W1 0                // 3*64   dup'd transposed
#define OFF_B1 192              // 64
#define OFF_W2 256              // 32*64
#define OFF_B2 2304             // 64
#define OFF_W3 2368             // 32*64
#define OFF_B3 4416             // 64
#define OFF_W4 4480             // 32*2
#define OFF_B4 4544             // 2
#define OFF_PAR 4546            // 14: K0,K1,L0,L1,Ms,Ms2,K1L1 dup'd
#define SCR_F (8*PM)            // scratch starts after weights (36480 floats)
#define SMEM_FLOATS (SCR_F + 32*NT*2)
#define SMEM_BYTES (SMEM_FLOATS*4)
#define DTC 0.0166667f
#define NNR 0.3f

// ---------- packed f32x2 helpers ----------
__device__ __forceinline__ u64 fma2(u64 a, u64 b, u64 c) {
    u64 d; asm("fma.rn.f32x2 %0, %1, %2, %3;" : "=l"(d) : "l"(a), "l"(b), "l"(c)); return d;
}
__device__ __forceinline__ u64 mul2(u64 a, u64 b) {
    u64 d; asm("mul.rn.f32x2 %0, %1, %2;" : "=l"(d) : "l"(a), "l"(b)); return d;
}
__device__ __forceinline__ u64 add2(u64 a, u64 b) {
    u64 d; asm("add.rn.f32x2 %0, %1, %2;" : "=l"(d) : "l"(a), "l"(b)); return d;
}
__device__ __forceinline__ u64 pack2(float lo, float hi) {
    u64 r; asm("mov.b64 %0, {%1, %2};" : "=l"(r) : "r"(__float_as_uint(lo)), "r"(__float_as_uint(hi))); return r;
}
__device__ __forceinline__ void unpack2(u64 v, float& lo, float& hi) {
    unsigned a, b; asm("mov.b64 {%0, %1}, %2;" : "=r"(a), "=r"(b) : "l"(v));
    lo = __uint_as_float(a); hi = __uint_as_float(b);
}
__device__ __forceinline__ float tanh_ap(float x) {
    float y; asm("tanh.approx.f32 %0, %1;" : "=f"(y) : "f"(x)); return y;
}
// leaky_relu(x) = 0.505*x + 0.495*|x|  (slope 0.01 on negatives), fully packed
__device__ __forceinline__ u64 leaky2(u64 x, u64 c505, u64 c495) {
    u64 ax = x & 0x7FFFFFFF7FFFFFFFull;
    return fma2(x, c505, mul2(ax, c495));
}

// dense 32->32 layer: h (packed pairs, per-thread scratch) -> acc -> leaky -> scratch
__device__ __forceinline__ void layer32(const float* __restrict__ smW,
                                        const float* __restrict__ smB,
                                        u64* __restrict__ scrT,
                                        u64 c505, u64 c495) {
    u64 acc[32];
    const ulonglong2* bp = reinterpret_cast<const ulonglong2*>(smB);
#pragma unroll
    for (int j = 0; j < 16; j++) { ulonglong2 b = bp[j]; acc[2*j] = b.x; acc[2*j+1] = b.y; }
#pragma unroll 4
    for (int i = 0; i < 32; i++) {
        u64 h = scrT[i * NT];
        const ulonglong2* wp = reinterpret_cast<const ulonglong2*>(smW + i * 64);
#pragma unroll
        for (int j = 0; j < 16; j++) {
            ulonglong2 w = wp[j];
            acc[2*j]   = fma2(h, w.x, acc[2*j]);
            acc[2*j+1] = fma2(h, w.y, acc[2*j+1]);
        }
    }
#pragma unroll
    for (int o = 0; o < 32; o++) scrT[o * NT] = leaky2(acc[o], c505, c495);
}

// closed-form 2x2 expm + phi1 solve for one element
__device__ __forceinline__ void finalize(float Ks, float Bs, float s0, float s1,
                                         float Iv, float invI, float Bv, float Kv,
                                         float& o0, float& o1) {
    float A10 = -(Ks + Kv) * invI;
    float Dd  = 2.0f * sqrtf(fmaxf(Ks * Iv, 0.0f));
    float A11 = -(Dd + Bv) * invI;
    float B10 = Bs * invI;
    float a10 = A10 * DTC, a11 = A11 * DTC;
    float s = 0.5f * a11;
    float q = fmaf(s, s, DTC * a10);        // s^2 - det(Atilde)
    float c, kf;
    if (q >= 0.0f) {
        float w = sqrtf(q);
        c = coshf(w);
        kf = (w > 1e-4f) ? sinhf(w) / w : 1.0f + q * (1.0f / 6.0f);
    } else {
        float w = sqrtf(-q);
        c = __cosf(w);
        kf = (w > 1e-4f) ? __sinf(w) / w : 1.0f + q * (1.0f / 6.0f);
    }
    float es = __expf(s);
    float g  = es * fmaf(-s, kf, c);        // e^s (c - s k)
    float kk = es * kf;
    float Ad01 = kk * DTC;
    float Ad10 = kk * a10;
    float Ad11 = g + kk * a11;
    float v  = DTC * B10;
    float y1 = kk * v;                      // = r0 / DT
    float r1 = (Ad11 - 1.0f) * v;
    float y0 = (r1 - a11 * y1) / a10;       // a10 strictly negative, never ~0
    o0 = fmaf(g,    s0, fmaf(Ad01, s1, y0));
    o1 = fmaf(Ad10, s0, fmaf(Ad11, s1, y1));
}

__global__ __launch_bounds__(NT, 1)
void joint_kernel(const float* __restrict__ SS,  const float* __restrict__ AL,
                  const float* __restrict__ K0,  const float* __restrict__ K1,
                  const float* __restrict__ L0,  const float* __restrict__ L1,
                  const float* __restrict__ Ms,  const float* __restrict__ Ip,
                  const float* __restrict__ Bvp, const float* __restrict__ Kvp,
                  const float* __restrict__ W1,  const float* __restrict__ b1,
                  const float* __restrict__ W2,  const float* __restrict__ b2,
                  const float* __restrict__ W3,  const float* __restrict__ b3,
                  const float* __restrict__ W4,  const float* __restrict__ b4,
                  float* __restrict__ out, int B) {
    extern __shared__ float sm[];
    const int tid = threadIdx.x;

    // ---- build duplicated, transposed weight tables in shared ----
    for (int t = tid; t < 768; t += NT) {            // W1[m][o][i] -> WD1[m][i][2o{,+1}]
        int m = t / 96, r = t - m * 96, o = r / 3, i = r - o * 3;
        float v = W1[t]; int d = m * PM + OFF_W1 + i * 64 + 2 * o; sm[d] = v; sm[d+1] = v;
    }
    for (int t = tid; t < 8192; t += NT) {           // W2
        int m = t >> 10, r = t & 1023, o = r >> 5, i = r & 31;
        float v = W2[t]; int d = m * PM + OFF_W2 + i * 64 + 2 * o; sm[d] = v; sm[d+1] = v;
    }
    for (int t = tid; t < 8192; t += NT) {           // W3
        int m = t >> 10, r = t & 1023, o = r >> 5, i = r & 31;
        float v = W3[t]; int d = m * PM + OFF_W3 + i * 64 + 2 * o; sm[d] = v; sm[d+1] = v;
    }
    for (int t = tid; t < 256; t += NT) {            // W4[m][0][i]
        int m = t >> 5, i = t & 31;
        float v = W4[t]; int d = m * PM + OFF_W4 + 2 * i; sm[d] = v; sm[d+1] = v;
    }
    for (int t = tid; t < 256; t += NT) {            // b1
        int m = t >> 5, o = t & 31;
        float v = b1[t]; int d = m * PM + OFF_B1 + 2 * o; sm[d] = v; sm[d+1] = v;
    }
    for (int t = tid; t < 256; t += NT) {            // b2
        int m = t >> 5, o = t & 31;
        float v = b2[t]; int d = m * PM + OFF_B2 + 2 * o; sm[d] = v; sm[d+1] = v;
    }
    for (int t = tid; t < 256; t += NT) {            // b3
        int m = t >> 5, o = t & 31;
        float v = b3[t]; int d = m * PM + OFF_B3 + 2 * o; sm[d] = v; sm[d+1] = v;
    }
    if (tid < 8) {
        int m = tid;
        float v = b4[m]; int d = m * PM + OFF_B4; sm[d] = v; sm[d+1] = v;
        float k0 = K0[m], k1 = K1[m], l0 = L0[m], l1 = L1[m], ms = Ms[m];
        float* p = sm + m * PM + OFF_PAR;
        p[0] = k0; p[1] = k0;   p[2] = k1; p[3] = k1;
        p[4] = l0; p[5] = l0;   p[6] = l1; p[7] = l1;
        p[8] = ms; p[9] = ms;   p[10] = ms * ms; p[11] = ms * ms;
        p[12] = k1 * l1; p[13] = k1 * l1;
    }
    __syncthreads();

    const int pid = blockIdx.x * NT + tid;
    const int e0 = pid * 2;
    if (e0 >= B) return;
    const int e1 = (e0 + 1 < B) ? e0 + 1 : e0;

    const u64 c505 = pack2(0.505f, 0.505f);
    const u64 c495 = pack2(0.495f, 0.495f);

    const float Iv = __ldg(Ip), Bv = __ldg(Bvp), Kv = __ldg(Kvp);
    const float invI = 1.0f / Iv;

    const float2 ssA = reinterpret_cast<const float2*>(SS)[e0];
    const float2 ssB = reinterpret_cast<const float2*>(SS)[e1];
    const u64 pS0 = pack2(ssA.x, ssB.x);
    const u64 pS1 = pack2(ssA.y, ssB.y);

    u64* scrT = reinterpret_cast<u64*>(sm + SCR_F) + tid;

    u64 pKsum = 0ull, pBsum = 0ull;

#pragma unroll 1
    for (int m = 0; m < 8; m++) {
        const float* mb = sm + m * PM;
        const u64* par = reinterpret_cast<const u64*>(mb + OFF_PAR);
        const u64 K0d = par[0], K1d = par[1], L0d = par[2], L1d = par[3];
        const u64 Msd = par[4], Ms2d = par[5], K1L1d = par[6];

        float a0 = fminf(fmaxf(__ldg(&AL[(size_t)e0 * 8 + m]), 0.0f), 1.0f);
        float a1 = fminf(fmaxf(__ldg(&AL[(size_t)e1 * 8 + m]), 0.0f), 1.0f);
        const u64 pa  = pack2(a0, a1);
        const u64 pl  = mul2(pS0, Msd);
        const u64 pdl = mul2(pS1, Msd);

        // ---- layer 1 (3 -> 32) ----
        {
            u64 acc[32];
            const ulonglong2* bp = reinterpret_cast<const ulonglong2*>(mb + OFF_B1);
#pragma unroll
            for (int j = 0; j < 16; j++) { ulonglong2 b = bp[j]; acc[2*j] = b.x; acc[2*j+1] = b.y; }
            u64 x3[3] = { pl, pdl, pa };
#pragma unroll
            for (int i = 0; i < 3; i++) {
                const ulonglong2* wp = reinterpret_cast<const ulonglong2*>(mb + OFF_W1 + i * 64);
#pragma unroll
                for (int j = 0; j < 16; j++) {
                    ulonglong2 w = wp[j];
                    acc[2*j]   = fma2(x3[i], w.x, acc[2*j]);
                    acc[2*j+1] = fma2(x3[i], w.y, acc[2*j+1]);
                }
            }
#pragma unroll
            for (int o = 0; o < 32; o++) scrT[o * NT] = leaky2(acc[o], c505, c495);
        }

        // ---- layers 2,3 (32 -> 32) ----
        layer32(mb + OFF_W2, mb + OFF_B2, scrT, c505, c495);
        layer32(mb + OFF_W3, mb + OFF_B3, scrT, c505, c495);

        // ---- layer 4 (32 -> 1) + tanh ----
        u64 acc0 = *reinterpret_cast<const u64*>(mb + OFF_B4);
        u64 acc1 = 0ull, acc2 = 0ull, acc3 = 0ull;
        const u64* w4p = reinterpret_cast<const u64*>(mb + OFF_W4);
#pragma unroll 8
        for (int i = 0; i < 32; i += 4) {
            acc0 = fma2(scrT[(i+0) * NT], w4p[i+0], acc0);
            acc1 = fma2(scrT[(i+1) * NT], w4p[i+1], acc1);
            acc2 = fma2(scrT[(i+2) * NT], w4p[i+2], acc2);
            acc3 = fma2(scrT[(i+3) * NT], w4p[i+3], acc3);
        }
        u64 accP = add2(add2(acc0, acc1), add2(acc2, acc3));
        float t0, t1; unpack2(accP, t0, t1);
        float nn0 = NNR * tanh_ap(t0);
        float nn1 = NNR * tanh_ap(t1);

        // ---- muscle epilogue (packed) ----
        u64 pK = fma2(pa, K1d, K0d);                  // K0 + K1*a
        pKsum  = fma2(pK, Ms2d, pKsum);               // += Km
        u64 tL = fma2(pa, L1d, L0d);                  // L0 + L1*a
        u64 nabsl = pl | 0x8000000080000000ull;       // -|l|
        tL = add2(tL, nabsl);
        u64 pBF = mul2(pK, tL);
        u64 pa2 = mul2(pa, pa);
        u64 pnn = pack2(nn0, nn1);
        pBF = fma2(mul2(pa2, pnn), K1L1d, pBF);
        pBsum = fma2(pBF, Msd, pBsum);
    }

    // ---- per-element expm epilogue + store ----
    float Ks0, Ks1, Bs0, Bs1;
    unpack2(pKsum, Ks0, Ks1);
    unpack2(pBsum, Bs0, Bs1);

    float o00, o01, o10, o11;
    finalize(Ks0, Bs0, ssA.x, ssA.y, Iv, invI, Bv, Kv, o00, o01);
    finalize(Ks1, Bs1, ssB.x, ssB.y, Iv, invI, Bv, Kv, o10, o11);

    float2* seg2 = reinterpret_cast<float2*>(out + B);
    out[e0]  = o00;
    seg2[e0] = make_float2(o00, o01);
    if (e1 != e0) {
        out[e1]  = o10;
        seg2[e1] = make_float2(o10, o11);
    }
}

extern "C" void kernel_launch(void* const* d_in, const int* in_sizes, int n_in,
                              void* d_out, int out_size) {
    const float* SS  = (const float*)d_in[0];
    const float* AL  = (const float*)d_in[1];
    const float* K0  = (const float*)d_in[2];
    const float* K1  = (const float*)d_in[3];
    const float* L0  = (const float*)d_in[4];
    const float* L1  = (const float*)d_in[5];
    const float* Ms  = (const float*)d_in[6];
    const float* Ip  = (const float*)d_in[7];
    const float* Bv  = (const float*)d_in[8];
    const float* Kv  = (const float*)d_in[9];
    const float* W1  = (const float*)d_in[10];
    const float* b1  = (const float*)d_in[11];
    const float* W2  = (const float*)d_in[12];
    const float* b2  = (const float*)d_in[13];
    const float* W3  = (const float*)d_in[14];
    const float* b3  = (const float*)d_in[15];
    const float* W4  = (const float*)d_in[16];
    const float* b4  = (const float*)d_in[17];
    float* out = (float*)d_out;

    const int B = in_sizes[0] / 2;
    const int pairs = (B + 1) / 2;
    const int grid = (pairs + NT - 1) / NT;

    cudaFuncSetAttribute(joint_kernel, cudaFuncAttributeMaxDynamicSharedMemorySize, SMEM_BYTES);
    joint_kernel<<<grid, NT, SMEM_BYTES>>>(SS, AL, K0, K1, L0, L1, Ms, Ip, Bv, Kv,
                                           W1, b1, W2, b2, W3, b3, W4, b4, out, B);
}